// round 2
// baseline (speedup 1.0000x reference)
#include <cuda_runtime.h>
#include <cstdint>
#include <math.h>

// Problem constants
#define S_TOK 2048
#define HID   2048
#define NJ    24      // 3*E router outputs
#define NE    8
#define MAXROWS 5120  // 4096 slots + per-expert padding to 128
#define NTILES  40    // max row tiles of 128

// ---------------- device scratch (allocation-free rule: __device__ globals) ---
__device__ float g_mix[S_TOK * NJ];
__device__ int   g_idx[S_TOK * 2];
__device__ float g_score[S_TOK * 2];
__device__ int   g_perm[MAXROWS];
__device__ int   g_slotmap[S_TOK * 2];
__device__ int   g_tile_expert[48];
__device__ float g_fc1[(size_t)MAXROWS * 4096];
__device__ float g_inter[(size_t)MAXROWS * 2048];
__device__ float g_y[(size_t)MAXROWS * 2048];

// ---------------- helpers ----------------------------------------------------
__device__ __forceinline__ uint32_t f2tf(float f) {
    uint32_t u;
    asm("cvt.rna.tf32.f32 %0, %1;" : "=r"(u) : "f"(f));
    return u;
}
__device__ __forceinline__ void cp16(float* dst, const float* src) {
    uint32_t d = (uint32_t)__cvta_generic_to_shared(dst);
    asm volatile("cp.async.cg.shared.global [%0], [%1], 16;\n" :: "r"(d), "l"(src));
}

// ---------------- 1) router mix = X @ Wqkv^T  [2048 x 24] --------------------
__global__ __launch_bounds__(256) void gate_kernel(
    const float* __restrict__ X, const float* __restrict__ Wqkv)
{
    __shared__ float xs[128 * 17];
    __shared__ float ws[NJ * 17];
    int t = threadIdx.x;
    int tok0 = blockIdx.x * 128;
    int mgrp = t & 31;        // token group
    int jgrp = t >> 5;        // 0..7 -> 3 j's each
    int j0 = jgrp * 3;

    float acc[4][3];
#pragma unroll
    for (int i = 0; i < 4; i++)
#pragma unroll
        for (int j = 0; j < 3; j++) acc[i][j] = 0.f;

    for (int kc = 0; kc < HID; kc += 16) {
#pragma unroll
        for (int i = 0; i < 8; i++) {
            int lin = t + i * 256;
            int m = lin >> 4, k = lin & 15;
            xs[m * 17 + k] = X[(size_t)(tok0 + m) * HID + kc + k];
        }
        // FIX: NJ*16 = 384 > 256 threads; previous code dropped rows 16..23 (v proj)
        for (int lin = t; lin < NJ * 16; lin += 256) {
            int j = lin >> 4, k = lin & 15;
            ws[j * 17 + k] = Wqkv[(size_t)j * HID + kc + k];
        }
        __syncthreads();
#pragma unroll
        for (int k = 0; k < 16; k++) {
            float w0 = ws[(j0 + 0) * 17 + k];
            float w1 = ws[(j0 + 1) * 17 + k];
            float w2 = ws[(j0 + 2) * 17 + k];
#pragma unroll
            for (int i = 0; i < 4; i++) {
                float xv = xs[(mgrp + i * 32) * 17 + k];
                acc[i][0] += xv * w0;
                acc[i][1] += xv * w1;
                acc[i][2] += xv * w2;
            }
        }
        __syncthreads();
    }
#pragma unroll
    for (int i = 0; i < 4; i++)
#pragma unroll
        for (int j = 0; j < 3; j++)
            g_mix[(tok0 + mgrp + i * 32) * NJ + j0 + j] = acc[i][j];
}

// ---------------- 2) per-token router attention + top-2 ----------------------
__global__ void route_kernel()
{
    int s = blockIdx.x * blockDim.x + threadIdx.x;
    if (s >= S_TOK) return;
    float q[NE], kk[NE], v[NE];
#pragma unroll
    for (int i = 0; i < NE; i++) {
        q[i]  = g_mix[s * NJ + i];
        kk[i] = g_mix[s * NJ + 8 + i];
        v[i]  = g_mix[s * NJ + 16 + i];
    }
    float logit[NE];
#pragma unroll
    for (int i = 0; i < NE; i++) {
        float mx = -1e30f;
#pragma unroll
        for (int j = 0; j < NE; j++) mx = fmaxf(mx, q[i] * kk[j]);
        float se = 0.f, ac = 0.f;
#pragma unroll
        for (int j = 0; j < NE; j++) {
            float e = expf(q[i] * kk[j] - mx);
            se += e;
            ac += e * v[j];
        }
        logit[i] = ac / se;
    }
    // top-2, jax tie semantics (lowest index wins ties)
    int i0 = 0;
#pragma unroll
    for (int j = 1; j < NE; j++) if (logit[j] > logit[i0]) i0 = j;
    int i1 = -1;
#pragma unroll
    for (int j = 0; j < NE; j++) {
        if (j == i0) continue;
        if (i1 < 0 || logit[j] > logit[i1]) i1 = j;
    }
    float e1 = expf(logit[i1] - logit[i0]);
    float p0 = 1.f / (1.f + e1);
    g_idx[2 * s] = i0;
    g_idx[2 * s + 1] = i1;
    g_score[2 * s] = p0;
    g_score[2 * s + 1] = e1 * p0;
}

// ---------------- 3) stable scatter: counts -> padded offsets -> perm --------
__global__ void scatter_kernel()
{
    __shared__ int cnt[NE];
    __shared__ int off[NE];
    int t = threadIdx.x, warp = t >> 5, lane = t & 31;

    for (int i = t; i < MAXROWS; i += 256) g_perm[i] = 0;
    if (t < 48) g_tile_expert[t] = -1;
    __syncthreads();

    // pass 1: count
    int c = 0;
    for (int b = 0; b < S_TOK; b += 32) {
        int s = b + lane;
        int e0 = g_idx[2 * s], e1 = g_idx[2 * s + 1];
        bool m = (e0 == warp) || (e1 == warp);
        unsigned bal = __ballot_sync(0xffffffffu, m);
        c += __popc(bal);
    }
    if (lane == 0) cnt[warp] = c;
    __syncthreads();

    if (t == 0) {
        int rb = 0, tb = 0;
        for (int e = 0; e < NE; e++) {
            off[e] = rb;
            int nt = (cnt[e] + 127) >> 7;
            for (int i = 0; i < nt; i++) g_tile_expert[tb++] = e;
            rb += nt << 7;
        }
    }
    __syncthreads();

    // pass 2: stable scatter
    int base = off[warp];
    for (int b = 0; b < S_TOK; b += 32) {
        int s = b + lane;
        int e0 = g_idx[2 * s], e1 = g_idx[2 * s + 1];
        bool m0 = (e0 == warp), m1 = (e1 == warp);
        bool m = m0 || m1;
        unsigned bal = __ballot_sync(0xffffffffu, m);
        if (m) {
            int pos = base + __popc(bal & ((1u << lane) - 1u));
            g_perm[pos] = s;
            g_slotmap[2 * s + (m0 ? 0 : 1)] = pos;
        }
        base += __popc(bal);
    }
}

// ---------------- 4) grouped TF32 GEMM (used for fc1 and fc2) ----------------
#define BM 128
#define BN 128
#define BKK 16
#define AST 20    // A smem stride (floats): conflict-free + 16B aligned rows
#define BST 136   // B smem stride

__global__ __launch_bounds__(256, 2) void moe_gemm(
    const float* __restrict__ Apar, const float* __restrict__ Ball,
    int N, int mode)
{
    int tile = blockIdx.y;
    int e = g_tile_expert[tile];
    if (e < 0) return;
    const float* A = mode ? Apar : g_inter;
    float* C = mode ? g_fc1 : g_y;
    const float* B = Ball + (size_t)e * HID * N;
    int row0 = tile * BM;
    int col0 = blockIdx.x * BN;
    int t = threadIdx.x;

    __shared__ __align__(16) float As[2][BM * AST];
    __shared__ __align__(16) float Bs[2][BKK * BST];
    __shared__ int prow[BM];
    if (t < BM) prow[t] = mode ? g_perm[row0 + t] : (row0 + t);
    __syncthreads();

    // prologue: stage 0
    {
#pragma unroll
        for (int i = 0; i < 2; i++) {
            int lin = t + i * 256;
            int m = lin >> 2, kq = lin & 3;
            cp16(&As[0][m * AST + kq * 4], A + (size_t)prow[m] * HID + kq * 4);
        }
#pragma unroll
        for (int i = 0; i < 2; i++) {
            int lin = t + i * 256;
            int k = lin >> 5, nq = lin & 31;
            cp16(&Bs[0][k * BST + nq * 4], B + (size_t)k * N + col0 + nq * 4);
        }
        asm volatile("cp.async.commit_group;\n");
    }

    int wid = t >> 5, lane = t & 31;
    int wm = wid & 3, wn = wid >> 2;      // warp grid 4x2 -> warp tile 32x64
    int gid = lane >> 2, tig = lane & 3;

    float acc[2][8][4];
#pragma unroll
    for (int a = 0; a < 2; a++)
#pragma unroll
        for (int b = 0; b < 8; b++)
#pragma unroll
            for (int c2 = 0; c2 < 4; c2++) acc[a][b][c2] = 0.f;

    const int NIT = HID / BKK;  // 128
    for (int it = 0; it < NIT; it++) {
        int st = it & 1;
        asm volatile("cp.async.wait_group 0;\n");
        __syncthreads();
        if (it + 1 < NIT) {
            int kk = (it + 1) * BKK;
            int s2 = st ^ 1;
#pragma unroll
            for (int i = 0; i < 2; i++) {
                int lin = t + i * 256;
                int m = lin >> 2, kq = lin & 3;
                cp16(&As[s2][m * AST + kq * 4], A + (size_t)prow[m] * HID + kk + kq * 4);
            }
#pragma unroll
            for (int i = 0; i < 2; i++) {
                int lin = t + i * 256;
                int k = lin >> 5, nq = lin & 31;
                cp16(&Bs[s2][k * BST + nq * 4], B + (size_t)(kk + k) * N + col0 + nq * 4);
            }
            asm volatile("cp.async.commit_group;\n");
        }
#pragma unroll
        for (int ks = 0; ks < BKK; ks += 8) {
            uint32_t af[2][4];
#pragma unroll
            for (int mf = 0; mf < 2; mf++) {
                int m = wm * 32 + mf * 16;
                af[mf][0] = f2tf(As[st][(m + gid)     * AST + ks + tig]);
                af[mf][1] = f2tf(As[st][(m + gid + 8) * AST + ks + tig]);
                af[mf][2] = f2tf(As[st][(m + gid)     * AST + ks + tig + 4]);
                af[mf][3] = f2tf(As[st][(m + gid + 8) * AST + ks + tig + 4]);
            }
            uint32_t bf[8][2];
#pragma unroll
            for (int nf = 0; nf < 8; nf++) {
                int n = wn * 64 + nf * 8 + gid;
                bf[nf][0] = f2tf(Bs[st][(ks + tig)     * BST + n]);
                bf[nf][1] = f2tf(Bs[st][(ks + tig + 4) * BST + n]);
            }
#pragma unroll
            for (int mf = 0; mf < 2; mf++)
#pragma unroll
                for (int nf = 0; nf < 8; nf++)
                    asm volatile(
                        "mma.sync.aligned.m16n8k8.row.col.f32.tf32.tf32.f32 "
                        "{%0,%1,%2,%3},{%4,%5,%6,%7},{%8,%9},{%0,%1,%2,%3};"
                        : "+f"(acc[mf][nf][0]), "+f"(acc[mf][nf][1]),
                          "+f"(acc[mf][nf][2]), "+f"(acc[mf][nf][3])
                        : "r"(af[mf][0]), "r"(af[mf][1]), "r"(af[mf][2]), "r"(af[mf][3]),
                          "r"(bf[nf][0]), "r"(bf[nf][1]));
        }
        __syncthreads();
    }

    // epilogue
#pragma unroll
    for (int mf = 0; mf < 2; mf++) {
        int r = row0 + wm * 32 + mf * 16 + gid;
#pragma unroll
        for (int nf = 0; nf < 8; nf++) {
            int c = col0 + wn * 64 + nf * 8 + tig * 2;
            float2 v0 = make_float2(acc[mf][nf][0], acc[mf][nf][1]);
            float2 v1 = make_float2(acc[mf][nf][2], acc[mf][nf][3]);
            *(float2*)&C[(size_t)r * N + c] = v0;
            *(float2*)&C[(size_t)(r + 8) * N + c] = v1;
        }
    }
}

// ---------------- 5) GLU: inter = silu(g) * u --------------------------------
__global__ void glu_kernel()
{
    size_t idx = (size_t)blockIdx.x * 256 + threadIdx.x;   // MAXROWS*2048 total
    size_t r = idx >> 11;
    int f = (int)(idx & 2047);
    float g = g_fc1[r * 4096 + f];
    float u = g_fc1[r * 4096 + 2048 + f];
    g_inter[idx] = (g / (1.f + expf(-g))) * u;
}

// ---------------- 6) combine: out[s] = s0*y[slot0] + s1*y[slot1] -------------
__global__ void combine_kernel(float* __restrict__ out)
{
    int s = blockIdx.x;
    float s0 = g_score[2 * s], s1 = g_score[2 * s + 1];
    size_t a = (size_t)g_slotmap[2 * s] * 2048;
    size_t b = (size_t)g_slotmap[2 * s + 1] * 2048;
    for (int i = threadIdx.x * 4; i < 2048; i += 256 * 4) {
        float4 ya = *(const float4*)&g_y[a + i];
        float4 yb = *(const float4*)&g_y[b + i];
        float4 o;
        o.x = s0 * ya.x + s1 * yb.x;
        o.y = s0 * ya.y + s1 * yb.y;
        o.z = s0 * ya.z + s1 * yb.z;
        o.w = s0 * ya.w + s1 * yb.w;
        *(float4*)&out[(size_t)s * 2048 + i] = o;
    }
}

// ---------------- launch -----------------------------------------------------
extern "C" void kernel_launch(void* const* d_in, const int* in_sizes, int n_in,
                              void* d_out, int out_size)
{
    const float* X    = (const float*)d_in[0];  // [2048, 2048]
    const float* Wqkv = (const float*)d_in[1];  // [24, 2048]
    const float* W1   = (const float*)d_in[2];  // [8, 2048, 4096]
    const float* W2   = (const float*)d_in[3];  // [8, 2048, 2048]
    float* out = (float*)d_out;                 // [2048, 2048]

    gate_kernel<<<16, 256>>>(X, Wqkv);
    route_kernel<<<8, 256>>>();
    scatter_kernel<<<1, 256>>>();
    moe_gemm<<<dim3(32, NTILES), 256>>>(X, W1, 4096, 1);
    glu_kernel<<<(MAXROWS * 2048) / 256, 256>>>();
    moe_gemm<<<dim3(16, NTILES), 256>>>(nullptr, W2, 2048, 0);
    combine_kernel<<<S_TOK, 256>>>(out);
}

// round 3
// speedup vs baseline: 1.0041x; 1.0041x over previous
#include <cuda_runtime.h>
#include <cstdint>
#include <math.h>

// Problem constants
#define S_TOK 2048
#define HID   2048
#define NJ    24      // 3*E router outputs
#define NE    8
#define MAXROWS 5120  // 4096 slots + per-expert padding to 128
#define NTILES  40    // max row tiles of 128

// ---------------- device scratch (allocation-free rule: __device__ globals) ---
__device__ float g_mix[S_TOK * NJ];
__device__ int   g_idx[S_TOK * 2];
__device__ float g_score[S_TOK * 2];
__device__ int   g_perm[MAXROWS];
__device__ int   g_slotmap[S_TOK * 2];
__device__ int   g_tile_expert[48];
__device__ float g_fc1[(size_t)MAXROWS * 4096];
__device__ float g_inter[(size_t)MAXROWS * 2048];
__device__ float g_y[(size_t)MAXROWS * 2048];

// ---------------- helpers ----------------------------------------------------
__device__ __forceinline__ uint32_t f2tf(float f) {
    uint32_t u;
    asm("cvt.rna.tf32.f32 %0, %1;" : "=r"(u) : "f"(f));
    return u;
}
__device__ __forceinline__ void cp16(float* dst, const float* src) {
    uint32_t d = (uint32_t)__cvta_generic_to_shared(dst);
    asm volatile("cp.async.cg.shared.global [%0], [%1], 16;\n" :: "r"(d), "l"(src));
}

// ---------------- 1) router mix = X @ Wqkv^T  [2048 x 24] --------------------
__global__ __launch_bounds__(256) void gate_kernel(
    const float* __restrict__ X, const float* __restrict__ Wqkv)
{
    __shared__ float xs[128 * 17];
    __shared__ float ws[NJ * 17];
    int t = threadIdx.x;
    int tok0 = blockIdx.x * 128;
    int mgrp = t & 31;        // token group
    int jgrp = t >> 5;        // 0..7 -> 3 j's each
    int j0 = jgrp * 3;

    float acc[4][3];
#pragma unroll
    for (int i = 0; i < 4; i++)
#pragma unroll
        for (int j = 0; j < 3; j++) acc[i][j] = 0.f;

    for (int kc = 0; kc < HID; kc += 16) {
#pragma unroll
        for (int i = 0; i < 8; i++) {
            int lin = t + i * 256;
            int m = lin >> 4, k = lin & 15;
            xs[m * 17 + k] = X[(size_t)(tok0 + m) * HID + kc + k];
        }
        // FIX: NJ*16 = 384 > 256 threads; previous code dropped rows 16..23 (v proj)
        for (int lin = t; lin < NJ * 16; lin += 256) {
            int j = lin >> 4, k = lin & 15;
            ws[j * 17 + k] = Wqkv[(size_t)j * HID + kc + k];
        }
        __syncthreads();
#pragma unroll
        for (int k = 0; k < 16; k++) {
            float w0 = ws[(j0 + 0) * 17 + k];
            float w1 = ws[(j0 + 1) * 17 + k];
            float w2 = ws[(j0 + 2) * 17 + k];
#pragma unroll
            for (int i = 0; i < 4; i++) {
                float xv = xs[(mgrp + i * 32) * 17 + k];
                acc[i][0] += xv * w0;
                acc[i][1] += xv * w1;
                acc[i][2] += xv * w2;
            }
        }
        __syncthreads();
    }
#pragma unroll
    for (int i = 0; i < 4; i++)
#pragma unroll
        for (int j = 0; j < 3; j++)
            g_mix[(tok0 + mgrp + i * 32) * NJ + j0 + j] = acc[i][j];
}

// ---------------- 2) per-token router attention + top-2 ----------------------
__global__ void route_kernel()
{
    int s = blockIdx.x * blockDim.x + threadIdx.x;
    if (s >= S_TOK) return;
    float q[NE], kk[NE], v[NE];
#pragma unroll
    for (int i = 0; i < NE; i++) {
        q[i]  = g_mix[s * NJ + i];
        kk[i] = g_mix[s * NJ + 8 + i];
        v[i]  = g_mix[s * NJ + 16 + i];
    }
    float logit[NE];
#pragma unroll
    for (int i = 0; i < NE; i++) {
        float mx = -1e30f;
#pragma unroll
        for (int j = 0; j < NE; j++) mx = fmaxf(mx, q[i] * kk[j]);
        float se = 0.f, ac = 0.f;
#pragma unroll
        for (int j = 0; j < NE; j++) {
            float e = expf(q[i] * kk[j] - mx);
            se += e;
            ac += e * v[j];
        }
        logit[i] = ac / se;
    }
    // top-2, jax tie semantics (lowest index wins ties)
    int i0 = 0;
#pragma unroll
    for (int j = 1; j < NE; j++) if (logit[j] > logit[i0]) i0 = j;
    int i1 = -1;
#pragma unroll
    for (int j = 0; j < NE; j++) {
        if (j == i0) continue;
        if (i1 < 0 || logit[j] > logit[i1]) i1 = j;
    }
    float e1 = expf(logit[i1] - logit[i0]);
    float p0 = 1.f / (1.f + e1);
    g_idx[2 * s] = i0;
    g_idx[2 * s + 1] = i1;
    g_score[2 * s] = p0;
    g_score[2 * s + 1] = e1 * p0;
}

// ---------------- 3) stable scatter: counts -> padded offsets -> perm --------
__global__ void scatter_kernel()
{
    __shared__ int cnt[NE];
    __shared__ int off[NE];
    int t = threadIdx.x, warp = t >> 5, lane = t & 31;

    for (int i = t; i < MAXROWS; i += 256) g_perm[i] = 0;
    if (t < 48) g_tile_expert[t] = -1;
    __syncthreads();

    // pass 1: count
    int c = 0;
    for (int b = 0; b < S_TOK; b += 32) {
        int s = b + lane;
        int e0 = g_idx[2 * s], e1 = g_idx[2 * s + 1];
        bool m = (e0 == warp) || (e1 == warp);
        unsigned bal = __ballot_sync(0xffffffffu, m);
        c += __popc(bal);
    }
    if (lane == 0) cnt[warp] = c;
    __syncthreads();

    if (t == 0) {
        int rb = 0, tb = 0;
        for (int e = 0; e < NE; e++) {
            off[e] = rb;
            int nt = (cnt[e] + 127) >> 7;
            for (int i = 0; i < nt; i++) g_tile_expert[tb++] = e;
            rb += nt << 7;
        }
    }
    __syncthreads();

    // pass 2: stable scatter
    int base = off[warp];
    for (int b = 0; b < S_TOK; b += 32) {
        int s = b + lane;
        int e0 = g_idx[2 * s], e1 = g_idx[2 * s + 1];
        bool m0 = (e0 == warp), m1 = (e1 == warp);
        bool m = m0 || m1;
        unsigned bal = __ballot_sync(0xffffffffu, m);
        if (m) {
            int pos = base + __popc(bal & ((1u << lane) - 1u));
            g_perm[pos] = s;
            g_slotmap[2 * s + (m0 ? 0 : 1)] = pos;
        }
        base += __popc(bal);
    }
}

// ---------------- 4) grouped TF32 GEMM (used for fc1 and fc2) ----------------
#define BM 128
#define BN 128
#define BKK 16
#define AST 20    // A smem stride (floats): conflict-free + 16B aligned rows
#define BST 136   // B smem stride

__global__ __launch_bounds__(256, 2) void moe_gemm(
    const float* __restrict__ Apar, const float* __restrict__ Ball,
    int N, int mode)
{
    int tile = blockIdx.y;
    int e = g_tile_expert[tile];
    if (e < 0) return;
    const float* A = mode ? Apar : g_inter;
    float* C = mode ? g_fc1 : g_y;
    const float* B = Ball + (size_t)e * HID * N;
    int row0 = tile * BM;
    int col0 = blockIdx.x * BN;
    int t = threadIdx.x;

    __shared__ __align__(16) float As[2][BM * AST];
    __shared__ __align__(16) float Bs[2][BKK * BST];
    __shared__ int prow[BM];
    if (t < BM) prow[t] = mode ? g_perm[row0 + t] : (row0 + t);
    __syncthreads();

    // prologue: stage 0
    {
#pragma unroll
        for (int i = 0; i < 2; i++) {
            int lin = t + i * 256;
            int m = lin >> 2, kq = lin & 3;
            cp16(&As[0][m * AST + kq * 4], A + (size_t)prow[m] * HID + kq * 4);
        }
#pragma unroll
        for (int i = 0; i < 2; i++) {
            int lin = t + i * 256;
            int k = lin >> 5, nq = lin & 31;
            cp16(&Bs[0][k * BST + nq * 4], B + (size_t)k * N + col0 + nq * 4);
        }
        asm volatile("cp.async.commit_group;\n");
    }

    int wid = t >> 5, lane = t & 31;
    int wm = wid & 3, wn = wid >> 2;      // warp grid 4x2 -> warp tile 32x64
    int gid = lane >> 2, tig = lane & 3;

    float acc[2][8][4];
#pragma unroll
    for (int a = 0; a < 2; a++)
#pragma unroll
        for (int b = 0; b < 8; b++)
#pragma unroll
            for (int c2 = 0; c2 < 4; c2++) acc[a][b][c2] = 0.f;

    const int NIT = HID / BKK;  // 128
    for (int it = 0; it < NIT; it++) {
        int st = it & 1;
        asm volatile("cp.async.wait_group 0;\n");
        __syncthreads();
        if (it + 1 < NIT) {
            int kk = (it + 1) * BKK;
            int s2 = st ^ 1;
#pragma unroll
            for (int i = 0; i < 2; i++) {
                int lin = t + i * 256;
                int m = lin >> 2, kq = lin & 3;
                cp16(&As[s2][m * AST + kq * 4], A + (size_t)prow[m] * HID + kk + kq * 4);
            }
#pragma unroll
            for (int i = 0; i < 2; i++) {
                int lin = t + i * 256;
                int k = lin >> 5, nq = lin & 31;
                cp16(&Bs[s2][k * BST + nq * 4], B + (size_t)(kk + k) * N + col0 + nq * 4);
            }
            asm volatile("cp.async.commit_group;\n");
        }
#pragma unroll
        for (int ks = 0; ks < BKK; ks += 8) {
            uint32_t af[2][4];
#pragma unroll
            for (int mf = 0; mf < 2; mf++) {
                int m = wm * 32 + mf * 16;
                af[mf][0] = f2tf(As[st][(m + gid)     * AST + ks + tig]);
                af[mf][1] = f2tf(As[st][(m + gid + 8) * AST + ks + tig]);
                af[mf][2] = f2tf(As[st][(m + gid)     * AST + ks + tig + 4]);
                af[mf][3] = f2tf(As[st][(m + gid + 8) * AST + ks + tig + 4]);
            }
            uint32_t bf[8][2];
#pragma unroll
            for (int nf = 0; nf < 8; nf++) {
                int n = wn * 64 + nf * 8 + gid;
                bf[nf][0] = f2tf(Bs[st][(ks + tig)     * BST + n]);
                bf[nf][1] = f2tf(Bs[st][(ks + tig + 4) * BST + n]);
            }
#pragma unroll
            for (int mf = 0; mf < 2; mf++)
#pragma unroll
                for (int nf = 0; nf < 8; nf++)
                    asm volatile(
                        "mma.sync.aligned.m16n8k8.row.col.f32.tf32.tf32.f32 "
                        "{%0,%1,%2,%3},{%4,%5,%6,%7},{%8,%9},{%0,%1,%2,%3};"
                        : "+f"(acc[mf][nf][0]), "+f"(acc[mf][nf][1]),
                          "+f"(acc[mf][nf][2]), "+f"(acc[mf][nf][3])
                        : "r"(af[mf][0]), "r"(af[mf][1]), "r"(af[mf][2]), "r"(af[mf][3]),
                          "r"(bf[nf][0]), "r"(bf[nf][1]));
        }
        __syncthreads();
    }

    // epilogue
#pragma unroll
    for (int mf = 0; mf < 2; mf++) {
        int r = row0 + wm * 32 + mf * 16 + gid;
#pragma unroll
        for (int nf = 0; nf < 8; nf++) {
            int c = col0 + wn * 64 + nf * 8 + tig * 2;
            float2 v0 = make_float2(acc[mf][nf][0], acc[mf][nf][1]);
            float2 v1 = make_float2(acc[mf][nf][2], acc[mf][nf][3]);
            *(float2*)&C[(size_t)r * N + c] = v0;
            *(float2*)&C[(size_t)(r + 8) * N + c] = v1;
        }
    }
}

// ---------------- 5) GLU: inter = silu(g) * u --------------------------------
__global__ void glu_kernel()
{
    size_t idx = (size_t)blockIdx.x * 256 + threadIdx.x;   // MAXROWS*2048 total
    size_t r = idx >> 11;
    int f = (int)(idx & 2047);
    float g = g_fc1[r * 4096 + f];
    float u = g_fc1[r * 4096 + 2048 + f];
    g_inter[idx] = (g / (1.f + expf(-g))) * u;
}

// ---------------- 6) combine: out[s] = s0*y[slot0] + s1*y[slot1] -------------
__global__ void combine_kernel(float* __restrict__ out)
{
    int s = blockIdx.x;
    float s0 = g_score[2 * s], s1 = g_score[2 * s + 1];
    size_t a = (size_t)g_slotmap[2 * s] * 2048;
    size_t b = (size_t)g_slotmap[2 * s + 1] * 2048;
    for (int i = threadIdx.x * 4; i < 2048; i += 256 * 4) {
        float4 ya = *(const float4*)&g_y[a + i];
        float4 yb = *(const float4*)&g_y[b + i];
        float4 o;
        o.x = s0 * ya.x + s1 * yb.x;
        o.y = s0 * ya.y + s1 * yb.y;
        o.z = s0 * ya.z + s1 * yb.z;
        o.w = s0 * ya.w + s1 * yb.w;
        *(float4*)&out[(size_t)s * 2048 + i] = o;
    }
}

// ---------------- launch -----------------------------------------------------
extern "C" void kernel_launch(void* const* d_in, const int* in_sizes, int n_in,
                              void* d_out, int out_size)
{
    const float* X    = (const float*)d_in[0];  // [2048, 2048]
    const float* Wqkv = (const float*)d_in[1];  // [24, 2048]
    const float* W1   = (const float*)d_in[2];  // [8, 2048, 4096]
    const float* W2   = (const float*)d_in[3];  // [8, 2048, 2048]
    float* out = (float*)d_out;                 // [2048, 2048]

    gate_kernel<<<16, 256>>>(X, Wqkv);
    route_kernel<<<8, 256>>>();
    scatter_kernel<<<1, 256>>>();
    moe_gemm<<<dim3(32, NTILES), 256>>>(X, W1, 4096, 1);
    glu_kernel<<<(MAXROWS * 2048) / 256, 256>>>();
    moe_gemm<<<dim3(16, NTILES), 256>>>(nullptr, W2, 2048, 0);
    combine_kernel<<<S_TOK, 256>>>(out);
}